// round 6
// baseline (speedup 1.0000x reference)
#include <cuda_runtime.h>
#include <cuda_fp16.h>
#include <math_constants.h>

#define D     128
#define NMAX  50000
#define EMAX  1600000

// ---------------- device scratch (allocation-free, static) ----------------
__device__ int g_is64;
__device__ int g_src[EMAX];
__device__ int g_dst[EMAX];
__device__ __align__(16) int g_deg[NMAX + 4];
__device__ __align__(16) int g_start[NMAX + 4];
__device__ __align__(16) int g_cursor[NMAX + 4];
__device__ int g_csr_src[EMAX];

__device__ __align__(256) float  g_Q[(size_t)NMAX * D];    // [N,128] fp32
__device__ __align__(256) __half g_Kh[(size_t)NMAX * D];   // [N,128] fp16 (scores only)
__device__ __align__(256) float  g_V[(size_t)NMAX * D];    // [N,128] fp32 (exact)
__device__ __align__(256) float  g_H[(size_t)NMAX * D];    // layer-1 output

// ---------------- zero degree histogram + edge width detection (fused) ----
__global__ void k_init_csr(const unsigned* __restrict__ ei, int N) {
    int i = blockIdx.x * blockDim.x + threadIdx.x;
    if (i < N) g_deg[i] = 0;
    if (i == 0) {
        int is64 = 1;
        for (int j = 0; j < 64; j++)
            if (ei[2 * j + 1] != 0u) is64 = 0;
        g_is64 = is64;
    }
}

__global__ void k_convert(const void* __restrict__ ei, int E) {
    int i = blockIdx.x * blockDim.x + threadIdx.x;
    if (i >= E) return;
    int s, d;
    if (g_is64) {
        const long long* p = (const long long*)ei;
        s = (int)p[i];
        d = (int)p[(size_t)E + i];
    } else {
        const int* p = (const int*)ei;
        s = p[i];
        d = p[E + i];
    }
    g_src[i] = s;
    g_dst[i] = d;
    atomicAdd(&g_deg[d], 1);
}

// ---------------- fast single-block exclusive scan ----------------
__global__ void k_scan(int N) {
    __shared__ int warp_sums[32];
    __shared__ int s_carry;
    int tid = threadIdx.x, lane = tid & 31, wid = tid >> 5;
    if (tid == 0) s_carry = 0;
    __syncthreads();

    const int TILE = 4096;
    for (int base = 0; base < N; base += TILE) {
        int idx = base + tid * 4;
        int4 v = make_int4(0, 0, 0, 0);
        if (idx + 3 < N) v = *(const int4*)&g_deg[idx];
        else {
            if (idx + 0 < N) v.x = g_deg[idx + 0];
            if (idx + 1 < N) v.y = g_deg[idx + 1];
            if (idx + 2 < N) v.z = g_deg[idx + 2];
            if (idx + 3 < N) v.w = g_deg[idx + 3];
        }
        int t0 = v.x, t1 = t0 + v.y, t2 = t1 + v.z, t3 = t2 + v.w;
        int inc = t3;
#pragma unroll
        for (int o = 1; o < 32; o <<= 1) {
            int n = __shfl_up_sync(0xFFFFFFFFu, inc, o);
            if (lane >= o) inc += n;
        }
        if (lane == 31) warp_sums[wid] = inc;
        __syncthreads();
        if (wid == 0) {
            int ws = warp_sums[lane];
#pragma unroll
            for (int o = 1; o < 32; o <<= 1) {
                int n = __shfl_up_sync(0xFFFFFFFFu, ws, o);
                if (lane >= o) ws += n;
            }
            warp_sums[lane] = ws;
        }
        __syncthreads();
        int warp_off = wid ? warp_sums[wid - 1] : 0;
        int e0 = s_carry + warp_off + (inc - t3);
        int tile_total = warp_sums[31];

        if (idx + 3 < N) {
            int4 e = make_int4(e0, e0 + t0, e0 + t1, e0 + t2);
            *(int4*)&g_start[idx]  = e;
            *(int4*)&g_cursor[idx] = e;
        } else {
            if (idx + 0 < N) { g_start[idx + 0] = e0;      g_cursor[idx + 0] = e0;      }
            if (idx + 1 < N) { g_start[idx + 1] = e0 + t0; g_cursor[idx + 1] = e0 + t0; }
            if (idx + 2 < N) { g_start[idx + 2] = e0 + t1; g_cursor[idx + 2] = e0 + t1; }
            if (idx + 3 < N) { g_start[idx + 3] = e0 + t2; g_cursor[idx + 3] = e0 + t2; }
        }
        __syncthreads();
        if (tid == 0) s_carry += tile_total;
        __syncthreads();
    }
    if (tid == 0) g_start[N] = s_carry;
}

__global__ void k_scatter(int E) {
    int i = blockIdx.x * blockDim.x + threadIdx.x;
    if (i >= E) return;
    int d = g_dst[i];
    int pos = atomicAdd(&g_cursor[d], 1);
    g_csr_src[pos] = g_src[i];
}

// ---------------- fused QKV GEMM: C = X @ W^T + b ----------------
// wsel 0 -> Q (fp32), 1 -> K (fp16), 2 -> V (fp32).
__global__ void __launch_bounds__(256, 2)
k_gemm_qkv(const float* __restrict__ xin, int layer,
           const float* __restrict__ qw, const float* __restrict__ qb,
           const float* __restrict__ kw, const float* __restrict__ kb,
           const float* __restrict__ vw, const float* __restrict__ vb,
           int N) {
    const float* X = layer ? g_H : xin;
    __shared__ float As[16][132];
    __shared__ float Bs[16][132];

    int wsel = blockIdx.y;
    const float* W  = (wsel == 0) ? qw : (wsel == 1) ? kw : vw;
    const float* Bb = (wsel == 0) ? qb : (wsel == 1) ? kb : vb;

    int m0 = blockIdx.x * 128;
    int tid = threadIdx.x;
    int tx = tid & 15, ty = tid >> 4;

    float acc[8][8];
#pragma unroll
    for (int i = 0; i < 8; i++)
#pragma unroll
        for (int j = 0; j < 8; j++) acc[i][j] = 0.0f;

    for (int k0 = 0; k0 < D; k0 += 16) {
#pragma unroll
        for (int f = tid; f < 512; f += 256) {
            int r = f >> 2, kq = (f & 3) * 4;
            int gr = m0 + r;
            float4 v = make_float4(0.f, 0.f, 0.f, 0.f);
            if (gr < N) v = *(const float4*)(X + (size_t)gr * D + k0 + kq);
            As[kq + 0][r] = v.x; As[kq + 1][r] = v.y;
            As[kq + 2][r] = v.z; As[kq + 3][r] = v.w;
        }
#pragma unroll
        for (int f = tid; f < 512; f += 256) {
            int r = f >> 2, kq = (f & 3) * 4;
            float4 v = *(const float4*)(W + (size_t)r * D + k0 + kq);
            Bs[kq + 0][r] = v.x; Bs[kq + 1][r] = v.y;
            Bs[kq + 2][r] = v.z; Bs[kq + 3][r] = v.w;
        }
        __syncthreads();
#pragma unroll
        for (int k = 0; k < 16; k++) {
            float4 a0 = *(const float4*)&As[k][ty * 4];
            float4 a1 = *(const float4*)&As[k][64 + ty * 4];
            float4 b0 = *(const float4*)&Bs[k][tx * 4];
            float4 b1 = *(const float4*)&Bs[k][64 + tx * 4];
            float a[8] = {a0.x, a0.y, a0.z, a0.w, a1.x, a1.y, a1.z, a1.w};
            float b[8] = {b0.x, b0.y, b0.z, b0.w, b1.x, b1.y, b1.z, b1.w};
#pragma unroll
            for (int i = 0; i < 8; i++)
#pragma unroll
                for (int j = 0; j < 8; j++)
                    acc[i][j] += a[i] * b[j];
        }
        __syncthreads();
    }

#pragma unroll
    for (int gi = 0; gi < 2; gi++) {
#pragma unroll
        for (int i = 0; i < 4; i++) {
            int gr = m0 + gi * 64 + ty * 4 + i;
            if (gr >= N) continue;
            int ai = gi * 4 + i;
#pragma unroll
            for (int gj = 0; gj < 2; gj++) {
                int gc = gj * 64 + tx * 4;
                int aj = gj * 4;
                float4 o;
                o.x = acc[ai][aj + 0] + Bb[gc + 0];
                o.y = acc[ai][aj + 1] + Bb[gc + 1];
                o.z = acc[ai][aj + 2] + Bb[gc + 2];
                o.w = acc[ai][aj + 3] + Bb[gc + 3];
                if (wsel == 1) {                  // K -> fp16
                    __half2 h01 = __floats2half2_rn(o.x, o.y);
                    __half2 h23 = __floats2half2_rn(o.z, o.w);
                    uint2 pk;
                    pk.x = *(unsigned*)&h01;
                    pk.y = *(unsigned*)&h23;
                    *(uint2*)(g_Kh + (size_t)gr * D + gc) = pk;
                } else {
                    float* C = (wsel == 0) ? g_Q : g_V;
                    *(float4*)(C + (size_t)gr * D + gc) = o;
                }
            }
        }
    }
}

// ---------------- fused attention: warp per dst node, online softmax ------
__global__ void k_attn(float* __restrict__ dout, int layer, int N) {
    int gw = (blockIdx.x * blockDim.x + threadIdx.x) >> 5;
    int lane = threadIdx.x & 31;
    if (gw >= N) return;

    float* outp = layer ? dout : g_H;

    int beg = g_start[gw], end = g_start[gw + 1];
    float4 q = ((const float4*)(g_Q + (size_t)gw * D))[lane];

    float m = -CUDART_INF_F, s = 0.0f;
    float4 acc = make_float4(0.f, 0.f, 0.f, 0.f);

    uint2  kf;
    float4 vf;
    if (beg < end) {
        int sp = g_csr_src[beg];
        kf = ((const uint2*)(g_Kh + (size_t)sp * D))[lane];
        vf = ((const float4*)(g_V + (size_t)sp * D))[lane];
    }

    for (int e = beg; e < end; e++) {
        uint2 kc = kf;
        float4 vc = vf;
        if (e + 1 < end) {                      // prefetch next edge
            int sp = g_csr_src[e + 1];
            kf = ((const uint2*)(g_Kh + (size_t)sp * D))[lane];
            vf = ((const float4*)(g_V + (size_t)sp * D))[lane];
        }
        float2 k01 = __half22float2(*(__half2*)&kc.x);
        float2 k23 = __half22float2(*(__half2*)&kc.y);
        float p = k01.x * q.x + k01.y * q.y + k23.x * q.z + k23.y * q.w;
#pragma unroll
        for (int o = 16; o; o >>= 1) p += __shfl_xor_sync(0xFFFFFFFFu, p, o);
        p *= 0.08838834764831845f;              // 1/sqrt(128)

        float mn = fmaxf(m, p);
        float c  = __expf(m - mn);              // exp(-inf)=0 on first edge
        float ep = __expf(p - mn);
        s = s * c + ep;
        acc.x = acc.x * c + ep * vc.x;
        acc.y = acc.y * c + ep * vc.y;
        acc.z = acc.z * c + ep * vc.z;
        acc.w = acc.w * c + ep * vc.w;
        m = mn;
    }

    float inv = (s > 0.0f) ? 1.0f / s : 0.0f;   // deg==0 -> zeros (matches ref)
    float4 o = make_float4(acc.x * inv, acc.y * inv, acc.z * inv, acc.w * inv);
    if (!layer) {                                // ELU fused into layer-1 epilogue
        o.x = (o.x > 0.f) ? o.x : expm1f(o.x);
        o.y = (o.y > 0.f) ? o.y : expm1f(o.y);
        o.z = (o.z > 0.f) ? o.z : expm1f(o.z);
        o.w = (o.w > 0.f) ? o.w : expm1f(o.w);
    }
    ((float4*)(outp + (size_t)gw * D))[lane] = o;
}

// ---------------- launch: fork CSR build alongside GEMM-1 ----------------
extern "C" void kernel_launch(void* const* d_in, const int* in_sizes, int n_in,
                              void* d_out, int out_size) {
    const float* x   = (const float*)d_in[0];
    const void*  ei  = d_in[1];
    const float* q1w = (const float*)d_in[2];  const float* q1b = (const float*)d_in[3];
    const float* k1w = (const float*)d_in[4];  const float* k1b = (const float*)d_in[5];
    const float* v1w = (const float*)d_in[6];  const float* v1b = (const float*)d_in[7];
    const float* q2w = (const float*)d_in[8];  const float* q2b = (const float*)d_in[9];
    const float* k2w = (const float*)d_in[10]; const float* k2b = (const float*)d_in[11];
    const float* v2w = (const float*)d_in[12]; const float* v2b = (const float*)d_in[13];

    int N = in_sizes[0] / D;
    int E = in_sizes[1] / 2;
    float* out = (float*)d_out;

    int eb = (E + 255) / 256;
    int nb = (N + 255) / 256;

    cudaStream_t s2;
    cudaEvent_t evFork, evJoin;
    cudaStreamCreateWithFlags(&s2, cudaStreamNonBlocking);
    cudaEventCreateWithFlags(&evFork, cudaEventDisableTiming);
    cudaEventCreateWithFlags(&evJoin, cudaEventDisableTiming);

    // fork: CSR build on s2 (depends only on edge_index)
    cudaEventRecord(evFork, 0);
    cudaStreamWaitEvent(s2, evFork, 0);
    k_init_csr<<<nb, 256, 0, s2>>>((const unsigned*)ei, N);
    k_convert<<<eb, 256, 0, s2>>>(ei, E);
    k_scan<<<1, 1024, 0, s2>>>(N);
    k_scatter<<<eb, 256, 0, s2>>>(E);
    cudaEventRecord(evJoin, s2);

    dim3 ggrid((N + 127) / 128, 3);
    int ab = (N * 32 + 255) / 256;

    // GEMM-1 runs concurrently with the CSR build
    k_gemm_qkv<<<ggrid, 256>>>(x, 0, q1w, q1b, k1w, k1b, v1w, v1b, N);

    // join: attention needs both
    cudaStreamWaitEvent(0, evJoin, 0);
    k_attn<<<ab, 256>>>(out, 0, N);

    // layer 2
    k_gemm_qkv<<<ggrid, 256>>>(x, 1, q2w, q2b, k2w, k2b, v2w, v2b, N);
    k_attn<<<ab, 256>>>(out, 1, N);
}

// round 7
// speedup vs baseline: 1.0119x; 1.0119x over previous
#include <cuda_runtime.h>
#include <math_constants.h>

#define D     128
#define NMAX  50000
#define EMAX  1600000

// ---------------- device scratch (allocation-free, static) ----------------
__device__ int g_is64;
__device__ int g_src[EMAX];
__device__ int g_dst[EMAX];
__device__ __align__(16) int g_deg[NMAX + 4];
__device__ __align__(16) int g_start[NMAX + 4];
__device__ __align__(16) int g_cursor[NMAX + 4];
__device__ int g_csr_src[EMAX];

__device__ __align__(256) float g_Q[(size_t)NMAX * D];        // [N,128]
__device__ __align__(256) float g_KV[(size_t)NMAX * 2 * D];   // [N,256]: K | V interleaved
__device__ __align__(256) float g_H[(size_t)NMAX * D];        // layer-1 output

// ---------------- zero degree histogram + edge width detection (fused) ----
__global__ void k_init_csr(const unsigned* __restrict__ ei, int N) {
    int i = blockIdx.x * blockDim.x + threadIdx.x;
    if (i < N) g_deg[i] = 0;
    if (i == 0) {
        int is64 = 1;
        for (int j = 0; j < 64; j++)
            if (ei[2 * j + 1] != 0u) is64 = 0;
        g_is64 = is64;
    }
}

__global__ void k_convert(const void* __restrict__ ei, int E) {
    int i = blockIdx.x * blockDim.x + threadIdx.x;
    if (i >= E) return;
    int s, d;
    if (g_is64) {
        const long long* p = (const long long*)ei;
        s = (int)p[i];
        d = (int)p[(size_t)E + i];
    } else {
        const int* p = (const int*)ei;
        s = p[i];
        d = p[E + i];
    }
    g_src[i] = s;
    g_dst[i] = d;
    atomicAdd(&g_deg[d], 1);
}

// ---------------- fast single-block exclusive scan ----------------
__global__ void k_scan(int N) {
    __shared__ int warp_sums[32];
    __shared__ int s_carry;
    int tid = threadIdx.x, lane = tid & 31, wid = tid >> 5;
    if (tid == 0) s_carry = 0;
    __syncthreads();

    const int TILE = 4096;
    for (int base = 0; base < N; base += TILE) {
        int idx = base + tid * 4;
        int4 v = make_int4(0, 0, 0, 0);
        if (idx + 3 < N) v = *(const int4*)&g_deg[idx];
        else {
            if (idx + 0 < N) v.x = g_deg[idx + 0];
            if (idx + 1 < N) v.y = g_deg[idx + 1];
            if (idx + 2 < N) v.z = g_deg[idx + 2];
            if (idx + 3 < N) v.w = g_deg[idx + 3];
        }
        int t0 = v.x, t1 = t0 + v.y, t2 = t1 + v.z, t3 = t2 + v.w;
        int inc = t3;
#pragma unroll
        for (int o = 1; o < 32; o <<= 1) {
            int n = __shfl_up_sync(0xFFFFFFFFu, inc, o);
            if (lane >= o) inc += n;
        }
        if (lane == 31) warp_sums[wid] = inc;
        __syncthreads();
        if (wid == 0) {
            int ws = warp_sums[lane];
#pragma unroll
            for (int o = 1; o < 32; o <<= 1) {
                int n = __shfl_up_sync(0xFFFFFFFFu, ws, o);
                if (lane >= o) ws += n;
            }
            warp_sums[lane] = ws;
        }
        __syncthreads();
        int warp_off = wid ? warp_sums[wid - 1] : 0;
        int e0 = s_carry + warp_off + (inc - t3);
        int tile_total = warp_sums[31];

        if (idx + 3 < N) {
            int4 e = make_int4(e0, e0 + t0, e0 + t1, e0 + t2);
            *(int4*)&g_start[idx]  = e;
            *(int4*)&g_cursor[idx] = e;
        } else {
            if (idx + 0 < N) { g_start[idx + 0] = e0;      g_cursor[idx + 0] = e0;      }
            if (idx + 1 < N) { g_start[idx + 1] = e0 + t0; g_cursor[idx + 1] = e0 + t0; }
            if (idx + 2 < N) { g_start[idx + 2] = e0 + t1; g_cursor[idx + 2] = e0 + t1; }
            if (idx + 3 < N) { g_start[idx + 3] = e0 + t2; g_cursor[idx + 3] = e0 + t2; }
        }
        __syncthreads();
        if (tid == 0) s_carry += tile_total;
        __syncthreads();
    }
    if (tid == 0) g_start[N] = s_carry;
}

__global__ void k_scatter(int E) {
    int i = blockIdx.x * blockDim.x + threadIdx.x;
    if (i >= E) return;
    int d = g_dst[i];
    int pos = atomicAdd(&g_cursor[d], 1);
    g_csr_src[pos] = g_src[i];
}

// ---------------- fused QKV GEMM: C = X @ W^T + b ----------------
__global__ void __launch_bounds__(256, 2)
k_gemm_qkv(const float* __restrict__ xin, int layer,
           const float* __restrict__ qw, const float* __restrict__ qb,
           const float* __restrict__ kw, const float* __restrict__ kb,
           const float* __restrict__ vw, const float* __restrict__ vb,
           int N) {
    const float* X = layer ? g_H : xin;
    __shared__ float As[16][132];
    __shared__ float Bs[16][132];

    int wsel = blockIdx.y;
    const float* W  = (wsel == 0) ? qw : (wsel == 1) ? kw : vw;
    const float* Bb = (wsel == 0) ? qb : (wsel == 1) ? kb : vb;
    float* C;
    int cs;
    if (wsel == 0)      { C = g_Q;        cs = 128; }
    else if (wsel == 1) { C = g_KV;       cs = 256; }
    else                { C = g_KV + 128; cs = 256; }

    int m0 = blockIdx.x * 128;
    int tid = threadIdx.x;
    int tx = tid & 15, ty = tid >> 4;

    float acc[8][8];
#pragma unroll
    for (int i = 0; i < 8; i++)
#pragma unroll
        for (int j = 0; j < 8; j++) acc[i][j] = 0.0f;

    for (int k0 = 0; k0 < D; k0 += 16) {
#pragma unroll
        for (int f = tid; f < 512; f += 256) {
            int r = f >> 2, kq = (f & 3) * 4;
            int gr = m0 + r;
            float4 v = make_float4(0.f, 0.f, 0.f, 0.f);
            if (gr < N) v = *(const float4*)(X + (size_t)gr * D + k0 + kq);
            As[kq + 0][r] = v.x; As[kq + 1][r] = v.y;
            As[kq + 2][r] = v.z; As[kq + 3][r] = v.w;
        }
#pragma unroll
        for (int f = tid; f < 512; f += 256) {
            int r = f >> 2, kq = (f & 3) * 4;
            float4 v = *(const float4*)(W + (size_t)r * D + k0 + kq);
            Bs[kq + 0][r] = v.x; Bs[kq + 1][r] = v.y;
            Bs[kq + 2][r] = v.z; Bs[kq + 3][r] = v.w;
        }
        __syncthreads();
#pragma unroll
        for (int k = 0; k < 16; k++) {
            float4 a0 = *(const float4*)&As[k][ty * 4];
            float4 a1 = *(const float4*)&As[k][64 + ty * 4];
            float4 b0 = *(const float4*)&Bs[k][tx * 4];
            float4 b1 = *(const float4*)&Bs[k][64 + tx * 4];
            float a[8] = {a0.x, a0.y, a0.z, a0.w, a1.x, a1.y, a1.z, a1.w};
            float b[8] = {b0.x, b0.y, b0.z, b0.w, b1.x, b1.y, b1.z, b1.w};
#pragma unroll
            for (int i = 0; i < 8; i++)
#pragma unroll
                for (int j = 0; j < 8; j++)
                    acc[i][j] += a[i] * b[j];
        }
        __syncthreads();
    }

#pragma unroll
    for (int gi = 0; gi < 2; gi++) {
#pragma unroll
        for (int i = 0; i < 4; i++) {
            int gr = m0 + gi * 64 + ty * 4 + i;
            if (gr >= N) continue;
            int ai = gi * 4 + i;
#pragma unroll
            for (int gj = 0; gj < 2; gj++) {
                int gc = gj * 64 + tx * 4;
                int aj = gj * 4;
                float4 o;
                o.x = acc[ai][aj + 0] + Bb[gc + 0];
                o.y = acc[ai][aj + 1] + Bb[gc + 1];
                o.z = acc[ai][aj + 2] + Bb[gc + 2];
                o.w = acc[ai][aj + 3] + Bb[gc + 3];
                *(float4*)(C + (size_t)gr * cs + gc) = o;
            }
        }
    }
}

// ---------------- fused attention: warp per dst node, online softmax ------
// 2 independent softmax states (A,B) processing edge pairs: 2x ILP on the
// shuffle chain, 4 outstanding gathers. Merged at the end.
__global__ void k_attn(float* __restrict__ dout, int layer, int N) {
    int gw = (blockIdx.x * blockDim.x + threadIdx.x) >> 5;
    int lane = threadIdx.x & 31;
    if (gw >= N) return;

    float* outp = layer ? dout : g_H;

    int beg = g_start[gw], end = g_start[gw + 1];
    float4 q = ((const float4*)(g_Q + (size_t)gw * D))[lane];

    float mA = -CUDART_INF_F, sA = 0.0f;
    float mB = -CUDART_INF_F, sB = 0.0f;
    float4 accA = make_float4(0.f, 0.f, 0.f, 0.f);
    float4 accB = make_float4(0.f, 0.f, 0.f, 0.f);

    float4 kA, vA, kB, vB;
    if (beg < end) {
        const float4* kv = (const float4*)(g_KV + (size_t)g_csr_src[beg] * 256);
        kA = kv[lane]; vA = kv[32 + lane];
    }
    if (beg + 1 < end) {
        const float4* kv = (const float4*)(g_KV + (size_t)g_csr_src[beg + 1] * 256);
        kB = kv[lane]; vB = kv[32 + lane];
    }

    for (int e = beg; e < end; e += 2) {
        float4 kcA = kA, vcA = vA, kcB = kB, vcB = vB;
        int hasB = (e + 1 < end);
        if (e + 2 < end) {                       // prefetch next pair (MLP 4)
            const float4* kv = (const float4*)(g_KV + (size_t)g_csr_src[e + 2] * 256);
            kA = kv[lane]; vA = kv[32 + lane];
        }
        if (e + 3 < end) {
            const float4* kv = (const float4*)(g_KV + (size_t)g_csr_src[e + 3] * 256);
            kB = kv[lane]; vB = kv[32 + lane];
        }

        float pA = kcA.x * q.x + kcA.y * q.y + kcA.z * q.z + kcA.w * q.w;
        float pB = kcB.x * q.x + kcB.y * q.y + kcB.z * q.z + kcB.w * q.w;
#pragma unroll
        for (int o = 16; o; o >>= 1) {           // two independent chains overlap
            pA += __shfl_xor_sync(0xFFFFFFFFu, pA, o);
            pB += __shfl_xor_sync(0xFFFFFFFFu, pB, o);
        }
        pA *= 0.08838834764831845f;              // 1/sqrt(128)
        pB *= 0.08838834764831845f;

        float mnA = fmaxf(mA, pA);
        float cA  = __expf(mA - mnA);
        float eA  = __expf(pA - mnA);
        sA = sA * cA + eA;
        accA.x = accA.x * cA + eA * vcA.x;
        accA.y = accA.y * cA + eA * vcA.y;
        accA.z = accA.z * cA + eA * vcA.z;
        accA.w = accA.w * cA + eA * vcA.w;
        mA = mnA;

        if (hasB) {
            float mnB = fmaxf(mB, pB);
            float cB  = __expf(mB - mnB);
            float eB  = __expf(pB - mnB);
            sB = sB * cB + eB;
            accB.x = accB.x * cB + eB * vcB.x;
            accB.y = accB.y * cB + eB * vcB.y;
            accB.z = accB.z * cB + eB * vcB.z;
            accB.w = accB.w * cB + eB * vcB.w;
            mB = mnB;
        }
    }

    // merge B into A (sB==0 -> skip; avoids -inf - -inf NaN)
    float m = mA, s = sA;
    float4 acc = accA;
    if (sB > 0.0f) {
        m = fmaxf(mA, mB);
        float cA = __expf(mA - m), cB = __expf(mB - m);
        s = sA * cA + sB * cB;
        acc.x = accA.x * cA + accB.x * cB;
        acc.y = accA.y * cA + accB.y * cB;
        acc.z = accA.z * cA + accB.z * cB;
        acc.w = accA.w * cA + accB.w * cB;
    }

    float inv = (s > 0.0f) ? 1.0f / s : 0.0f;    // deg==0 -> zeros (matches ref)
    float4 o = make_float4(acc.x * inv, acc.y * inv, acc.z * inv, acc.w * inv);
    if (!layer) {                                 // ELU fused into layer-1 epilogue
        o.x = (o.x > 0.f) ? o.x : expm1f(o.x);
        o.y = (o.y > 0.f) ? o.y : expm1f(o.y);
        o.z = (o.z > 0.f) ? o.z : expm1f(o.z);
        o.w = (o.w > 0.f) ? o.w : expm1f(o.w);
    }
    ((float4*)(outp + (size_t)gw * D))[lane] = o;
}

// ---------------- launch: fork CSR build alongside GEMM-1 ----------------
extern "C" void kernel_launch(void* const* d_in, const int* in_sizes, int n_in,
                              void* d_out, int out_size) {
    const float* x   = (const float*)d_in[0];
    const void*  ei  = d_in[1];
    const float* q1w = (const float*)d_in[2];  const float* q1b = (const float*)d_in[3];
    const float* k1w = (const float*)d_in[4];  const float* k1b = (const float*)d_in[5];
    const float* v1w = (const float*)d_in[6];  const float* v1b = (const float*)d_in[7];
    const float* q2w = (const float*)d_in[8];  const float* q2b = (const float*)d_in[9];
    const float* k2w = (const float*)d_in[10]; const float* k2b = (const float*)d_in[11];
    const float* v2w = (const float*)d_in[12]; const float* v2b = (const float*)d_in[13];

    int N = in_sizes[0] / D;
    int E = in_sizes[1] / 2;
    float* out = (float*)d_out;

    int eb = (E + 255) / 256;
    int nb = (N + 255) / 256;

    cudaStream_t s2;
    cudaEvent_t evFork, evJoin;
    cudaStreamCreateWithFlags(&s2, cudaStreamNonBlocking);
    cudaEventCreateWithFlags(&evFork, cudaEventDisableTiming);
    cudaEventCreateWithFlags(&evJoin, cudaEventDisableTiming);

    // fork: CSR build on s2 (depends only on edge_index)
    cudaEventRecord(evFork, 0);
    cudaStreamWaitEvent(s2, evFork, 0);
    k_init_csr<<<nb, 256, 0, s2>>>((const unsigned*)ei, N);
    k_convert<<<eb, 256, 0, s2>>>(ei, E);
    k_scan<<<1, 1024, 0, s2>>>(N);
    k_scatter<<<eb, 256, 0, s2>>>(E);
    cudaEventRecord(evJoin, s2);

    dim3 ggrid((N + 127) / 128, 3);
    int ab = (N * 32 + 255) / 256;

    // GEMM-1 runs concurrently with the CSR build
    k_gemm_qkv<<<ggrid, 256>>>(x, 0, q1w, q1b, k1w, k1b, v1w, v1b, N);

    // join: attention needs both
    cudaStreamWaitEvent(0, evJoin, 0);
    k_attn<<<ab, 256>>>(out, 0, N);

    // layer 2
    k_gemm_qkv<<<ggrid, 256>>>(x, 1, q2w, q2b, k2w, k2b, v2w, v2b, N);
    k_attn<<<ab, 256>>>(out, 1, N);
}